// round 3
// baseline (speedup 1.0000x reference)
#include <cuda_runtime.h>
#include <stdint.h>

#define BS 32
#define N 512
#define IN_X 16
#define IN_E 5
#define IN_C 3
#define IN_BD 3
#define OUT_X 16
#define OUT_E 5
#define OUT_C 3
#define OUT_BD 3

#define XCAT_OFF   0
#define XCAT_SZ    (BS * N * (IN_X + OUT_X))          // 524288
#define CCAT_OFF   (XCAT_OFF + XCAT_SZ)
#define CCAT_SZ    (BS * N * (IN_C + OUT_C))          // 98304
#define E1_OFF     (CCAT_OFF + CCAT_SZ)               // 622592
#define E1_SZ      (BS * N * N * OUT_E)               // 41943040
#define E2_OFF     (E1_OFF + E1_SZ)
#define BD1_OFF    (E2_OFF + E1_SZ)

#define SLICE_CAP  256                                 // max staged product span

// ---------------------------------------------------------------------------
// One block per (sample i, reactant row j1). Rebuilds the per-sample
// alignment map in smem, then stages the contiguous product slice of E/BD in
// smem (coalesced) and gathers from smem (LDS) instead of scattered LDG.
// ---------------------------------------------------------------------------
__global__ __launch_bounds__(256) void fused_kernel(
    const float* __restrict__ X,
    const float* __restrict__ E,
    const float* __restrict__ AC,
    const float* __restrict__ BD,
    const int*   __restrict__ AMN,
    const int*   __restrict__ MA,
    float* __restrict__ out)
{
    __shared__ int   s_amn[N];
    __shared__ int   s_ma[N];
    __shared__ int   s_table[N + 1];      // table[m] = product pos + 1
    __shared__ int   s_sp[N];             // prodpos per reactant slot
    __shared__ int   s_max, s_plo, s_phi;
    __shared__ float sE[SLICE_CAP * IN_E];    // 5120 B
    __shared__ float sBD[SLICE_CAP * IN_BD];  // 3072 B

    const int b   = blockIdx.x;
    const int i   = b >> 9;
    const int j1  = b & (N - 1);
    const int tid = threadIdx.x;

    // ---- per-sample alignment prep ----
    if (tid == 0) { s_max = -2147483647; s_plo = N; s_phi = -1; s_table[N] = 0; }
    int mymax = -2147483647;
    #pragma unroll
    for (int k = 0; k < N / 256; k++) {
        const int j = tid + k * 256;
        const int a = AMN[i * N + j];
        const int m = MA[i * N + j];
        s_amn[j] = a;
        s_ma[j]  = m;
        s_table[j] = 0;
        mymax = max(mymax, m);
    }
    #pragma unroll
    for (int off = 16; off; off >>= 1)
        mymax = max(mymax, __shfl_xor_sync(0xffffffffu, mymax, off));
    __syncthreads();
    if ((tid & 31) == 0) atomicMax(&s_max, mymax);
    __syncthreads();
    const int pa = s_max;

    // product-side scatter + product-span reduction
    int myplo = N, myphi = -1;
    #pragma unroll
    for (int k = 0; k < N / 256; k++) {
        const int j = tid + k * 256;
        const int a = s_amn[j];
        if (s_ma[j] == pa) {
            myplo = min(myplo, j);
            myphi = max(myphi, j);
            if (a > 0 && a <= N) s_table[a] = j + 1;
        }
    }
    #pragma unroll
    for (int off = 16; off; off >>= 1) {
        myplo = min(myplo, __shfl_xor_sync(0xffffffffu, myplo, off));
        myphi = max(myphi, __shfl_xor_sync(0xffffffffu, myphi, off));
    }
    if ((tid & 31) == 0) { atomicMin(&s_plo, myplo); atomicMax(&s_phi, myphi); }
    __syncthreads();

    // this row's aligned product position
    int p1 = -1;
    {
        const int a = s_amn[j1];
        if (s_ma[j1] < pa && a > 0 && a <= N) {
            const int t = s_table[a];
            if (t > 0) p1 = t - 1;
        }
    }

    const int row = b;
    float* __restrict__ e1r = out + E1_OFF  + (size_t)row * (N * OUT_E);
    float* __restrict__ e2r = out + E2_OFF  + (size_t)row * (N * OUT_E);
    float* __restrict__ bdr = out + BD1_OFF + (size_t)row * (N * OUT_BD);

    // ---- node features (38 floats for this row) ----
    if (tid < 32) {
        float v;
        if (tid < IN_X) v = X[row * IN_X + tid];
        else            v = (p1 >= 0) ? __ldg(&X[(i * N + p1) * IN_X + (tid - IN_X)]) : 0.0f;
        out[XCAT_OFF + row * (IN_X + OUT_X) + tid] = v;
    } else if (tid < 38) {
        const int c = tid - 32;
        float v;
        if (c < IN_C) v = AC[row * IN_C + c];
        else          v = (p1 >= 0) ? __ldg(&AC[(i * N + p1) * IN_C + (c - IN_C)]) : 0.0f;
        out[CCAT_OFF + row * (IN_C + OUT_C) + c] = v;
    }

    float4* __restrict__ e1v = reinterpret_cast<float4*>(e1r);
    float4* __restrict__ e2v = reinterpret_cast<float4*>(e2r);
    float4* __restrict__ bdv = reinterpret_cast<float4*>(bdr);

    if (p1 < 0) {
        // ---- unmapped row: vectorized fills only ----
        const float4 z4 = make_float4(0.f, 0.f, 0.f, 0.f);
        float4 pat[5];
        pat[0] = make_float4(1.f, 0.f, 0.f, 0.f);
        pat[1] = make_float4(0.f, 1.f, 0.f, 0.f);
        pat[2] = make_float4(0.f, 0.f, 1.f, 0.f);
        pat[3] = make_float4(0.f, 0.f, 0.f, 1.f);
        pat[4] = z4;
        #pragma unroll
        for (int k = tid; k < (N * OUT_E) / 4; k += 256) {
            __stcs(&e1v[k], z4);
            __stcs(&e2v[k], pat[k % 5]);
        }
        #pragma unroll
        for (int k = tid; k < (N * OUT_BD) / 4; k += 256) {
            __stcs(&bdv[k], z4);
        }
        return;
    }

    // ---- mapped row ----
    // build full prodpos table
    #pragma unroll
    for (int k = 0; k < N / 256; k++) {
        const int j = tid + k * 256;
        const int a = s_amn[j];
        int pp = -1;
        if (s_ma[j] < pa && a > 0 && a <= N) {
            const int t = s_table[a];
            if (t > 0) pp = t - 1;
        }
        s_sp[j] = pp;
    }

    const int pLo  = s_plo;
    int span = s_phi - pLo + 1;
    if (span > SLICE_CAP) span = SLICE_CAP;

    const float* __restrict__ Erow  = E  + (size_t)(i * N + p1) * N * IN_E;
    const float* __restrict__ BDrow = BD + (size_t)(i * N + p1) * N * IN_BD;

    // stage contiguous product slices into smem (coalesced)
    {
        const float* __restrict__ Es  = Erow  + (size_t)pLo * IN_E;
        const float* __restrict__ BDs = BDrow + (size_t)pLo * IN_BD;
        const int nE  = span * IN_E;     // <= 1280
        const int nBD = span * IN_BD;    // <= 768
        for (int t = tid; t < nE; t += 256)  sE[t]  = __ldg(&Es[t]);
        for (int t = tid; t < nBD; t += 256) sBD[t] = __ldg(&BDs[t]);
    }
    __syncthreads();

    // E1 / E2: 640 float4 per row, gather from smem
    for (int k = tid; k < (N * OUT_E) / 4; k += 256) {
        float v1[4], v2[4];
        const int e0 = 4 * k;
        #pragma unroll
        for (int c4 = 0; c4 < 4; c4++) {
            const int ee = e0 + c4;
            const int j2 = ee / 5;
            const int c  = ee - j2 * 5;
            const int p2 = s_sp[j2];
            if (p2 >= 0) {
                const int idx = p2 - pLo;
                v1[c4] = (idx >= 0 && idx < span) ? sE[idx * IN_E + c]
                                                  : __ldg(&Erow[p2 * IN_E + c]);
                v2[c4] = 0.0f;
            } else {
                v1[c4] = 0.0f;
                v2[c4] = (c == 0) ? 1.0f : 0.0f;
            }
        }
        __stcs(&e1v[k], make_float4(v1[0], v1[1], v1[2], v1[3]));
        __stcs(&e2v[k], make_float4(v2[0], v2[1], v2[2], v2[3]));
    }

    // BD1: 384 float4 per row
    for (int k = tid; k < (N * OUT_BD) / 4; k += 256) {
        float v[4];
        const int e0 = 4 * k;
        #pragma unroll
        for (int c4 = 0; c4 < 4; c4++) {
            const int ee = e0 + c4;
            const int j2 = ee / 3;
            const int c  = ee - j2 * 3;
            const int p2 = s_sp[j2];
            float vv = 0.0f;
            if (p2 >= 0) {
                const int idx = p2 - pLo;
                vv = (idx >= 0 && idx < span) ? sBD[idx * IN_BD + c]
                                              : __ldg(&BDrow[p2 * IN_BD + c]);
            }
            v[c4] = vv;
        }
        __stcs(&bdv[k], make_float4(v[0], v[1], v[2], v[3]));
    }
}

// ---------------------------------------------------------------------------
extern "C" void kernel_launch(void* const* d_in, const int* in_sizes, int n_in,
                              void* d_out, int out_size) {
    const float* X   = (const float*)d_in[0];
    const float* E   = (const float*)d_in[1];
    const float* AC  = (const float*)d_in[2];
    const float* BD  = (const float*)d_in[3];
    const int*   AMN = (const int*)d_in[4];
    const int*   MA  = (const int*)d_in[5];
    float* out = (float*)d_out;

    fused_kernel<<<BS * N, 256>>>(X, E, AC, BD, AMN, MA, out);
}